// round 3
// baseline (speedup 1.0000x reference)
#include <cuda_runtime.h>

#define KBINS 8
#define TAILB 12.0f
#define MIN_BW 1e-6f
#define MIN_BH 1e-6f
#define MIN_DD 1e-6f

// layer index tables
__device__ __constant__ int MI0c[4] = {0, 1, 0, 2};
__device__ __constant__ int MI1c[4] = {2, 3, 1, 3};
__device__ __constant__ int II0c[4] = {1, 0, 2, 0};
__device__ __constant__ int II1c[4] = {3, 2, 3, 1};

__device__ __forceinline__ unsigned long long fma2(unsigned long long a,
                                                   unsigned long long b,
                                                   unsigned long long c) {
    unsigned long long d;
    asm("fma.rn.f32x2 %0, %1, %2, %3;" : "=l"(d) : "l"(a), "l"(b), "l"(c));
    return d;
}
__device__ __forceinline__ float lo32(unsigned long long a) {
    return __uint_as_float((unsigned)(a & 0xffffffffull));
}
__device__ __forceinline__ float hi32(unsigned long long a) {
    return __uint_as_float((unsigned)(a >> 32));
}
__device__ __forceinline__ float softplusf(float x) {
    return fmaxf(x, 0.0f) + log1pf(expf(-fabsf(x)));
}

// Shared-memory word offsets (floats)
#define OFF_H1   0        // 16*514 = 8224
#define OFF_H2   8224     // 8224
#define OFF_W2   16448    // 16384
#define OFF_W3   32832    // 48*128 = 6144
#define OFF_W1   38976    // 384
#define OFF_B1   39360    // 128
#define OFF_B2   39488    // 128
#define OFF_B3   39616    // 48
#define OFF_XS   39664    // 256
#define OFF_CS   39920    // 64
#define OFF_PB   39984    // 64*48 = 3072
#define OFF_LAD  43056    // 128
#define OFF_LDT  43184    // 64
#define SMEM_FLOATS 43248 // 172,992 bytes

__global__ __launch_bounds__(256)
void rqs_fused_kernel(const float* __restrict__ inputs,
                      const float* __restrict__ cond,
                      const float* __restrict__ W1, const float* __restrict__ b1,
                      const float* __restrict__ W2, const float* __restrict__ b2,
                      const float* __restrict__ W3, const float* __restrict__ b3,
                      float* __restrict__ out, int B)
{
    extern __shared__ float sm[];
    float* h1  = sm + OFF_H1;
    float* h2  = sm + OFF_H2;
    float* sW2 = sm + OFF_W2;
    float* sW3 = sm + OFF_W3;
    float* sW1 = sm + OFF_W1;
    float* sb1 = sm + OFF_B1;
    float* sb2 = sm + OFF_B2;
    float* sb3 = sm + OFF_B3;
    float* xs  = sm + OFF_XS;
    float* cs  = sm + OFF_CS;
    float* pb  = sm + OFF_PB;
    float* lad = sm + OFF_LAD;
    float* ldt = sm + OFF_LDT;

    const int t = threadIdx.x;
    const int base = blockIdx.x * 64;

    // load per-block inputs
    xs[t] = inputs[base * 4 + t];  // 256 threads = 64 samples * 4
    if (t < 64) { cs[t] = cond[base + t]; ldt[t] = 0.0f; }

    const int sg = t & 15;   // sample group: samples 4*sg .. 4*sg+3
    const int g  = t >> 4;   // output group 0..15

    #pragma unroll 1
    for (int l = 0; l < 4; l++) {
        __syncthreads();
        // ---- stage layer weights into smem ----
        {
            const float4* w2p = (const float4*)(W2 + l * 16384);
            float4* dW2 = (float4*)sW2;
            #pragma unroll
            for (int i = 0; i < 16; i++) dW2[t + i * 256] = w2p[t + i * 256];

            const float4* w3p = (const float4*)(W3 + l * 5888);
            float4* dW3 = (float4*)sW3;
            #pragma unroll
            for (int i = 0; i < 6; i++) {
                int idx = t + i * 256;
                if (idx < 1472) dW3[idx] = w3p[idx];
            }
            if (t < 64) dW3[1472 + t] = make_float4(0.f, 0.f, 0.f, 0.f);

            if (t < 96) ((float4*)sW1)[t] = ((const float4*)(W1 + l * 384))[t];
            if (t < 128) { sb1[t] = b1[l * 128 + t]; sb2[t] = b2[l * 128 + t]; }
            if (t < 48) sb3[t] = (t < 46) ? b3[l * 46 + t] : 0.0f;
        }
        __syncthreads();

        // ---- layer 1: h1 = relu([x_m0, x_m1, cond] @ W1^T + b1) ----
        {
            const int mi0 = MI0c[l], mi1 = MI1c[l];
            #pragma unroll
            for (int i = 0; i < 32; i++) {
                int idx = t + i * 256;
                int s = idx >> 7, h = idx & 127;
                float m0 = xs[s * 4 + mi0], m1 = xs[s * 4 + mi1], m2 = cs[s];
                float r = fmaf(sW1[h * 3], m0,
                          fmaf(sW1[h * 3 + 1], m1,
                          fmaf(sW1[h * 3 + 2], m2, sb1[h])));
                h1[(s >> 2) * 514 + (h >> 1) * 8 + (s & 3) * 2 + (h & 1)] = fmaxf(r, 0.0f);
            }
        }
        __syncthreads();

        // ---- GEMM2: h2 = relu(h1 @ W2^T + b2), packed f32x2 along k ----
        {
            const float* hb = h1 + sg * 514;
            const float* wb = sW2 + (g * 8) * 128;
            unsigned long long acc[8][4];
            #pragma unroll
            for (int jj = 0; jj < 8; jj++)
                #pragma unroll
                for (int si = 0; si < 4; si++) acc[jj][si] = 0ull;

            #pragma unroll 4
            for (int kp = 0; kp < 64; kp++) {
                unsigned long long hv0 = *(const unsigned long long*)(hb + kp * 8);
                unsigned long long hv1 = *(const unsigned long long*)(hb + kp * 8 + 2);
                unsigned long long hv2 = *(const unsigned long long*)(hb + kp * 8 + 4);
                unsigned long long hv3 = *(const unsigned long long*)(hb + kp * 8 + 6);
                #pragma unroll
                for (int jj = 0; jj < 8; jj++) {
                    unsigned long long wv =
                        *(const unsigned long long*)(wb + jj * 128 + kp * 2);
                    acc[jj][0] = fma2(wv, hv0, acc[jj][0]);
                    acc[jj][1] = fma2(wv, hv1, acc[jj][1]);
                    acc[jj][2] = fma2(wv, hv2, acc[jj][2]);
                    acc[jj][3] = fma2(wv, hv3, acc[jj][3]);
                }
            }
            #pragma unroll
            for (int jj = 0; jj < 8; jj++) {
                int j = g * 8 + jj;
                float bb = sb2[j];
                #pragma unroll
                for (int si = 0; si < 4; si++) {
                    float r = lo32(acc[jj][si]) + hi32(acc[jj][si]) + bb;
                    h2[sg * 514 + (j >> 1) * 8 + si * 2 + (j & 1)] = fmaxf(r, 0.0f);
                }
            }
        }
        __syncthreads();

        // ---- GEMM3: params = h2 @ W3^T + b3  (48 outputs, rows 46/47 zero) ----
        {
            const float* hb = h2 + sg * 514;
            const float* wb = sW3 + (g * 3) * 128;
            unsigned long long acc[3][4];
            #pragma unroll
            for (int jj = 0; jj < 3; jj++)
                #pragma unroll
                for (int si = 0; si < 4; si++) acc[jj][si] = 0ull;

            #pragma unroll 4
            for (int kp = 0; kp < 64; kp++) {
                unsigned long long hv0 = *(const unsigned long long*)(hb + kp * 8);
                unsigned long long hv1 = *(const unsigned long long*)(hb + kp * 8 + 2);
                unsigned long long hv2 = *(const unsigned long long*)(hb + kp * 8 + 4);
                unsigned long long hv3 = *(const unsigned long long*)(hb + kp * 8 + 6);
                #pragma unroll
                for (int jj = 0; jj < 3; jj++) {
                    unsigned long long wv =
                        *(const unsigned long long*)(wb + jj * 128 + kp * 2);
                    acc[jj][0] = fma2(wv, hv0, acc[jj][0]);
                    acc[jj][1] = fma2(wv, hv1, acc[jj][1]);
                    acc[jj][2] = fma2(wv, hv2, acc[jj][2]);
                    acc[jj][3] = fma2(wv, hv3, acc[jj][3]);
                }
            }
            #pragma unroll
            for (int jj = 0; jj < 3; jj++) {
                int j = g * 3 + jj;
                float bb = sb3[j];
                #pragma unroll
                for (int si = 0; si < 4; si++) {
                    pb[(sg * 4 + si) * 48 + j] =
                        lo32(acc[jj][si]) + hi32(acc[jj][si]) + bb;
                }
            }
        }
        __syncthreads();

        // ---- RQS spline: one thread per (sample, transformed-dim) ----
        if (t < 128) {
            const int s = t >> 1, f = t & 1;
            const int ii = f ? II1c[l] : II0c[l];
            const float* pp = pb + s * 48 + f;

            // widths (softmax)
            float uw[8];
            #pragma unroll
            for (int j = 0; j < 8; j++) uw[j] = pp[2 * j];
            float mw = uw[0];
            #pragma unroll
            for (int j = 1; j < 8; j++) mw = fmaxf(mw, uw[j]);
            float ew[8], swsum = 0.0f;
            #pragma unroll
            for (int j = 0; j < 8; j++) { ew[j] = expf(uw[j] - mw); swsum += ew[j]; }
            float scw = (1.0f - MIN_BW * 8.0f) / swsum;
            float cw[9];
            cw[0] = -TAILB;
            {
                float c = 0.0f;
                #pragma unroll
                for (int j = 0; j < 8; j++) {
                    c += MIN_BW + scw * ew[j];
                    cw[j + 1] = fmaf(2.0f * TAILB, c, -TAILB);
                }
            }
            cw[8] = TAILB;

            // heights (softmax)
            float uh[8];
            #pragma unroll
            for (int j = 0; j < 8; j++) uh[j] = pp[2 * (8 + j)];
            float mh = uh[0];
            #pragma unroll
            for (int j = 1; j < 8; j++) mh = fmaxf(mh, uh[j]);
            float eh[8], shsum = 0.0f;
            #pragma unroll
            for (int j = 0; j < 8; j++) { eh[j] = expf(uh[j] - mh); shsum += eh[j]; }
            float sch = (1.0f - MIN_BH * 8.0f) / shsum;
            float ch[9];
            ch[0] = -TAILB;
            {
                float c = 0.0f;
                #pragma unroll
                for (int j = 0; j < 8; j++) {
                    c += MIN_BH + sch * eh[j];
                    ch[j + 1] = fmaf(2.0f * TAILB, c, -TAILB);
                }
            }
            ch[8] = TAILB;

            // derivatives (boundary = exactly 1.0)
            float dv[9];
            dv[0] = 1.0f; dv[8] = 1.0f;
            #pragma unroll
            for (int j = 0; j < 7; j++)
                dv[j + 1] = MIN_DD + softplusf(pp[2 * (16 + j)]);

            float xv = xs[s * 4 + ii];
            bool inside = (xv >= -TAILB) && (xv <= TAILB);
            float xc = fminf(fmaxf(xv, -TAILB), TAILB);

            int bin = 0;
            #pragma unroll
            for (int i = 1; i < 8; i++) if (xc >= cw[i]) bin = i;

            float icw = cw[0], iw = cw[1] - cw[0];
            float ich = ch[0], ih = ch[1] - ch[0];
            float dk = dv[0], dk1 = dv[1];
            #pragma unroll
            for (int i = 1; i < 8; i++) if (bin == i) {
                icw = cw[i]; iw = cw[i + 1] - cw[i];
                ich = ch[i]; ih = ch[i + 1] - ch[i];
                dk = dv[i]; dk1 = dv[i + 1];
            }

            float th = (xc - icw) / iw;
            float delta = ih / iw;
            float omt = 1.0f - th;
            float tomt = th * omt;
            float num = ih * (delta * th * th + dk * tomt);
            float den = delta + (dk + dk1 - 2.0f * delta) * tomt;
            float y = ich + num / den;
            float dnum = delta * delta *
                         (dk1 * th * th + 2.0f * delta * tomt + dk * omt * omt);
            float ladv = logf(dnum) - 2.0f * logf(den);

            xs[s * 4 + ii] = inside ? y : xv;
            lad[t] = inside ? ladv : 0.0f;
        }
        __syncthreads();
        if (t < 64) ldt[t] += lad[2 * t] + lad[2 * t + 1];
    }

    __syncthreads();
    // outputs: x flattened [B,4] then logdets [B,1]
    out[base * 4 + t] = xs[t];
    if (t < 64) out[(size_t)B * 4 + base + t] = ldt[t];
}

extern "C" void kernel_launch(void* const* d_in, const int* in_sizes, int n_in,
                              void* d_out, int out_size)
{
    const float* inputs = (const float*)d_in[0];
    const float* cond   = (const float*)d_in[1];
    const float* W1     = (const float*)d_in[2];
    const float* b1     = (const float*)d_in[3];
    const float* W2     = (const float*)d_in[4];
    const float* b2     = (const float*)d_in[5];
    const float* W3     = (const float*)d_in[6];
    const float* b3     = (const float*)d_in[7];
    float* out = (float*)d_out;

    const int B = in_sizes[0] / 4;
    const int smem_bytes = SMEM_FLOATS * 4;
    cudaFuncSetAttribute(rqs_fused_kernel,
                         cudaFuncAttributeMaxDynamicSharedMemorySize, smem_bytes);
    rqs_fused_kernel<<<B / 64, 256, smem_bytes>>>(inputs, cond, W1, b1, W2, b2,
                                                  W3, b3, out, B);
}

// round 5
// speedup vs baseline: 1.0256x; 1.0256x over previous
#include <cuda_runtime.h>

#define KBINS 8
#define TAILB 12.0f
#define MIN_BW 1e-6f
#define MIN_BH 1e-6f
#define MIN_DD 1e-6f

// layer index tables
__device__ __constant__ int MI0c[4] = {0, 1, 0, 2};
__device__ __constant__ int MI1c[4] = {2, 3, 1, 3};
__device__ __constant__ int II0c[4] = {1, 0, 2, 0};
__device__ __constant__ int II1c[4] = {3, 2, 3, 1};

__device__ __forceinline__ unsigned long long fma2(unsigned long long a,
                                                   unsigned long long b,
                                                   unsigned long long c) {
    unsigned long long d;
    asm("fma.rn.f32x2 %0, %1, %2, %3;" : "=l"(d) : "l"(a), "l"(b), "l"(c));
    return d;
}
__device__ __forceinline__ float lo32(unsigned long long a) {
    return __uint_as_float((unsigned)(a & 0xffffffffull));
}
__device__ __forceinline__ float hi32(unsigned long long a) {
    return __uint_as_float((unsigned)(a >> 32));
}
__device__ __forceinline__ float softplusf(float x) {
    return fmaxf(x, 0.0f) + log1pf(expf(-fabsf(x)));
}

// Shared-memory word offsets (floats), 128 samples / block, 512 threads.
// pb (spline params, 128*48 = 6144) ALIASES h1 (dead after GEMM2).
#define OFF_H1   0        // 32*514 = 16448
#define OFF_PB   0        // aliases h1
#define OFF_H2   16448    // 16448
#define OFF_W2   32896    // 16384
#define OFF_W3   49280    // 48*128 = 6144
#define OFF_W1   55424    // 384
#define OFF_B1   55808    // 128
#define OFF_B2   55936    // 128
#define OFF_B3   56064    // 48
#define OFF_XS   56112    // 512
#define OFF_CS   56624    // 128
#define OFF_LAD  56752    // 256
#define OFF_LDT  57008    // 128
#define SMEM_FLOATS 57136 // 228,544 bytes

__global__ __launch_bounds__(512)
void rqs_fused_kernel(const float* __restrict__ inputs,
                      const float* __restrict__ cond,
                      const float* __restrict__ W1, const float* __restrict__ b1,
                      const float* __restrict__ W2, const float* __restrict__ b2,
                      const float* __restrict__ W3, const float* __restrict__ b3,
                      float* __restrict__ out, int B)
{
    extern __shared__ float sm[];
    float* h1  = sm + OFF_H1;
    float* h2  = sm + OFF_H2;
    float* sW2 = sm + OFF_W2;
    float* sW3 = sm + OFF_W3;
    float* sW1 = sm + OFF_W1;
    float* sb1 = sm + OFF_B1;
    float* sb2 = sm + OFF_B2;
    float* sb3 = sm + OFF_B3;
    float* xs  = sm + OFF_XS;
    float* cs  = sm + OFF_CS;
    float* pb  = sm + OFF_PB;
    float* lad = sm + OFF_LAD;
    float* ldt = sm + OFF_LDT;

    const int t = threadIdx.x;
    const int base = blockIdx.x * 128;

    // load per-block inputs (512 threads = 128 samples * 4)
    xs[t] = inputs[base * 4 + t];
    if (t < 128) { cs[t] = cond[base + t]; ldt[t] = 0.0f; }

    const int sg = t & 31;   // sample group: samples 4*sg .. 4*sg+3
    const int g  = t >> 5;   // output group 0..15 (uniform per warp)

    #pragma unroll 1
    for (int l = 0; l < 4; l++) {
        __syncthreads();
        // ---- stage layer weights into smem ----
        {
            const float4* w2p = (const float4*)(W2 + l * 16384);
            float4* dW2 = (float4*)sW2;
            #pragma unroll
            for (int i = 0; i < 8; i++) dW2[t + i * 512] = w2p[t + i * 512];

            const float4* w3p = (const float4*)(W3 + l * 5888);
            float4* dW3 = (float4*)sW3;
            #pragma unroll
            for (int i = 0; i < 3; i++) {
                int idx = t + i * 512;
                if (idx < 1472) dW3[idx] = w3p[idx];
            }
            if (t < 64) dW3[1472 + t] = make_float4(0.f, 0.f, 0.f, 0.f);

            if (t < 96) ((float4*)sW1)[t] = ((const float4*)(W1 + l * 384))[t];
            if (t < 128) { sb1[t] = b1[l * 128 + t]; sb2[t] = b2[l * 128 + t]; }
            if (t < 48) sb3[t] = (t < 46) ? b3[l * 46 + t] : 0.0f;
        }
        __syncthreads();

        // ---- layer 1: h1 = relu([x_m0, x_m1, cond] @ W1^T + b1) ----
        {
            const int mi0 = MI0c[l], mi1 = MI1c[l];
            #pragma unroll
            for (int i = 0; i < 32; i++) {
                int idx = t + i * 512;
                int s = idx >> 7, h = idx & 127;
                float m0 = xs[s * 4 + mi0], m1 = xs[s * 4 + mi1], m2 = cs[s];
                float r = fmaf(sW1[h * 3], m0,
                          fmaf(sW1[h * 3 + 1], m1,
                          fmaf(sW1[h * 3 + 2], m2, sb1[h])));
                h1[(s >> 2) * 514 + (h >> 1) * 8 + (s & 3) * 2 + (h & 1)] = fmaxf(r, 0.0f);
            }
        }
        __syncthreads();

        // ---- GEMM2: h2 = relu(h1 @ W2^T + b2), packed f32x2 along k ----
        {
            const float* hb = h1 + sg * 514;
            const float* wb = sW2 + (g * 8) * 128;
            unsigned long long acc[8][4];
            #pragma unroll
            for (int jj = 0; jj < 8; jj++)
                #pragma unroll
                for (int si = 0; si < 4; si++) acc[jj][si] = 0ull;

            #pragma unroll 4
            for (int kp = 0; kp < 64; kp++) {
                unsigned long long hv0 = *(const unsigned long long*)(hb + kp * 8);
                unsigned long long hv1 = *(const unsigned long long*)(hb + kp * 8 + 2);
                unsigned long long hv2 = *(const unsigned long long*)(hb + kp * 8 + 4);
                unsigned long long hv3 = *(const unsigned long long*)(hb + kp * 8 + 6);
                #pragma unroll
                for (int jj = 0; jj < 8; jj++) {
                    unsigned long long wv =
                        *(const unsigned long long*)(wb + jj * 128 + kp * 2);
                    acc[jj][0] = fma2(wv, hv0, acc[jj][0]);
                    acc[jj][1] = fma2(wv, hv1, acc[jj][1]);
                    acc[jj][2] = fma2(wv, hv2, acc[jj][2]);
                    acc[jj][3] = fma2(wv, hv3, acc[jj][3]);
                }
            }
            #pragma unroll
            for (int jj = 0; jj < 8; jj++) {
                int j = g * 8 + jj;
                float bb = sb2[j];
                #pragma unroll
                for (int si = 0; si < 4; si++) {
                    float r = lo32(acc[jj][si]) + hi32(acc[jj][si]) + bb;
                    h2[sg * 514 + (j >> 1) * 8 + si * 2 + (j & 1)] = fmaxf(r, 0.0f);
                }
            }
        }
        __syncthreads();

        // ---- GEMM3: params = h2 @ W3^T + b3  (48 outputs, rows 46/47 zero) ----
        // NOTE: writes pb, which aliases h1 (h1 dead after GEMM2; barrier above).
        {
            const float* hb = h2 + sg * 514;
            const float* wb = sW3 + (g * 3) * 128;
            unsigned long long acc[3][4];
            #pragma unroll
            for (int jj = 0; jj < 3; jj++)
                #pragma unroll
                for (int si = 0; si < 4; si++) acc[jj][si] = 0ull;

            #pragma unroll 4
            for (int kp = 0; kp < 64; kp++) {
                unsigned long long hv0 = *(const unsigned long long*)(hb + kp * 8);
                unsigned long long hv1 = *(const unsigned long long*)(hb + kp * 8 + 2);
                unsigned long long hv2 = *(const unsigned long long*)(hb + kp * 8 + 4);
                unsigned long long hv3 = *(const unsigned long long*)(hb + kp * 8 + 6);
                #pragma unroll
                for (int jj = 0; jj < 3; jj++) {
                    unsigned long long wv =
                        *(const unsigned long long*)(wb + jj * 128 + kp * 2);
                    acc[jj][0] = fma2(wv, hv0, acc[jj][0]);
                    acc[jj][1] = fma2(wv, hv1, acc[jj][1]);
                    acc[jj][2] = fma2(wv, hv2, acc[jj][2]);
                    acc[jj][3] = fma2(wv, hv3, acc[jj][3]);
                }
            }
            #pragma unroll
            for (int jj = 0; jj < 3; jj++) {
                int j = g * 3 + jj;
                float bb = sb3[j];
                #pragma unroll
                for (int si = 0; si < 4; si++) {
                    pb[(sg * 4 + si) * 48 + j] =
                        lo32(acc[jj][si]) + hi32(acc[jj][si]) + bb;
                }
            }
        }
        __syncthreads();

        // ---- RQS spline: one thread per (sample, transformed-dim) ----
        if (t < 256) {
            const int s = t >> 1, f = t & 1;
            const int ii = f ? II1c[l] : II0c[l];
            const float* pp = pb + s * 48 + f;

            // widths (softmax)
            float uw[8];
            #pragma unroll
            for (int j = 0; j < 8; j++) uw[j] = pp[2 * j];
            float mw = uw[0];
            #pragma unroll
            for (int j = 1; j < 8; j++) mw = fmaxf(mw, uw[j]);
            float ew[8], swsum = 0.0f;
            #pragma unroll
            for (int j = 0; j < 8; j++) { ew[j] = expf(uw[j] - mw); swsum += ew[j]; }
            float scw = (1.0f - MIN_BW * 8.0f) / swsum;
            float cw[9];
            cw[0] = -TAILB;
            {
                float c = 0.0f;
                #pragma unroll
                for (int j = 0; j < 8; j++) {
                    c += MIN_BW + scw * ew[j];
                    cw[j + 1] = fmaf(2.0f * TAILB, c, -TAILB);
                }
            }
            cw[8] = TAILB;

            // heights (softmax)
            float uh[8];
            #pragma unroll
            for (int j = 0; j < 8; j++) uh[j] = pp[2 * (8 + j)];
            float mh = uh[0];
            #pragma unroll
            for (int j = 1; j < 8; j++) mh = fmaxf(mh, uh[j]);
            float eh[8], shsum = 0.0f;
            #pragma unroll
            for (int j = 0; j < 8; j++) { eh[j] = expf(uh[j] - mh); shsum += eh[j]; }
            float sch = (1.0f - MIN_BH * 8.0f) / shsum;
            float ch[9];
            ch[0] = -TAILB;
            {
                float c = 0.0f;
                #pragma unroll
                for (int j = 0; j < 8; j++) {
                    c += MIN_BH + sch * eh[j];
                    ch[j + 1] = fmaf(2.0f * TAILB, c, -TAILB);
                }
            }
            ch[8] = TAILB;

            // derivatives (boundary = exactly 1.0)
            float dv[9];
            dv[0] = 1.0f; dv[8] = 1.0f;
            #pragma unroll
            for (int j = 0; j < 7; j++)
                dv[j + 1] = MIN_DD + softplusf(pp[2 * (16 + j)]);

            float xv = xs[s * 4 + ii];
            bool inside = (xv >= -TAILB) && (xv <= TAILB);
            float xc = fminf(fmaxf(xv, -TAILB), TAILB);

            int bin = 0;
            #pragma unroll
            for (int i = 1; i < 8; i++) if (xc >= cw[i]) bin = i;

            float icw = cw[0], iw = cw[1] - cw[0];
            float ich = ch[0], ih = ch[1] - ch[0];
            float dk = dv[0], dk1 = dv[1];
            #pragma unroll
            for (int i = 1; i < 8; i++) if (bin == i) {
                icw = cw[i]; iw = cw[i + 1] - cw[i];
                ich = ch[i]; ih = ch[i + 1] - ch[i];
                dk = dv[i]; dk1 = dv[i + 1];
            }

            float th = (xc - icw) / iw;
            float delta = ih / iw;
            float omt = 1.0f - th;
            float tomt = th * omt;
            float num = ih * (delta * th * th + dk * tomt);
            float den = delta + (dk + dk1 - 2.0f * delta) * tomt;
            float y = ich + num / den;
            float dnum = delta * delta *
                         (dk1 * th * th + 2.0f * delta * tomt + dk * omt * omt);
            float ladv = logf(dnum) - 2.0f * logf(den);

            xs[s * 4 + ii] = inside ? y : xv;
            lad[t] = inside ? ladv : 0.0f;
        }
        __syncthreads();
        if (t < 128) ldt[t] += lad[2 * t] + lad[2 * t + 1];
    }

    __syncthreads();
    // outputs: x flattened [B,4] then logdets [B,1]
    out[base * 4 + t] = xs[t];
    if (t < 128) out[(size_t)B * 4 + base + t] = ldt[t];
}

extern "C" void kernel_launch(void* const* d_in, const int* in_sizes, int n_in,
                              void* d_out, int out_size)
{
    const float* inputs = (const float*)d_in[0];
    const float* cond   = (const float*)d_in[1];
    const float* W1     = (const float*)d_in[2];
    const float* b1     = (const float*)d_in[3];
    const float* W2     = (const float*)d_in[4];
    const float* b2     = (const float*)d_in[5];
    const float* W3     = (const float*)d_in[6];
    const float* b3     = (const float*)d_in[7];
    float* out = (float*)d_out;

    const int B = in_sizes[0] / 4;
    const int smem_bytes = SMEM_FLOATS * 4;  // 228,544 bytes
    cudaFuncSetAttribute(rqs_fused_kernel,
                         cudaFuncAttributeMaxDynamicSharedMemorySize, smem_bytes);
    rqs_fused_kernel<<<B / 128, 512, smem_bytes>>>(inputs, cond, W1, b1, W2, b2,
                                                   W3, b3, out, B);
}